// round 8
// baseline (speedup 1.0000x reference)
#include <cuda_runtime.h>
#include <cuda_bf16.h>
#include <math.h>
#include <stdint.h>

// Problem constants
#define PB   64
#define PT   2048
#define PH   256
#define PV   512
#define PVD  8
#define PD   128

// Scratch
__device__ float g_Xp[(size_t)PB * PT * PH];   // inputs @ W_ih.T + b
__device__ float g_H [(size_t)PB * PT * PH];   // hidden states
__device__ float g_Wfold[PH * PVD];            // W_hh @ W_sh  (256 x 8)

// ---- f32x2 packed-FMA helpers (sm_103a FFMA2) ------------------------------
#define FMA2(d,a,b,c) asm("fma.rn.f32x2 %0, %1, %2, %3;" : "=l"(d) : "l"(a), "l"(b), "l"(c))
#define ADD2(d,a,b)   asm("add.rn.f32x2 %0, %1, %2;"     : "=l"(d) : "l"(a), "l"(b))
#define PACK2(d,lo,hi) asm("mov.b64 %0, {%1, %2};" : "=l"(d) : "r"(__float_as_uint(lo)), "r"(__float_as_uint(hi)))
#define UNPACK2(lo,hi,s) do { unsigned _ulo, _uhi; \
    asm("mov.b64 {%0, %1}, %2;" : "=r"(_ulo), "=r"(_uhi) : "l"(s)); \
    lo = __uint_as_float(_ulo); hi = __uint_as_float(_uhi); } while (0)

__device__ __forceinline__ uint32_t s2u(const void* p) {
    uint32_t a;
    asm("{ .reg .u64 t; cvta.to.shared.u64 t, %1; cvt.u32.u64 %0, t; }" : "=r"(a) : "l"(p));
    return a;
}

__device__ __forceinline__ float fast_tanh(float x) {
    const float xc = fminf(fmaxf(x, -10.f), 10.f);
    const float e = __expf(2.f * xc);
    return __fdividef(e - 1.f, e + 1.f);
}
__device__ __forceinline__ float fast_sigmoid(float x) {
    return __fdividef(1.f, 1.f + __expf(-x));
}

// ---------------------------------------------------------------------------
__global__ void fold_kernel(const float* __restrict__ W_hh,
                            const float* __restrict__ W_sh)
{
    int idx = blockIdx.x * blockDim.x + threadIdx.x;
    if (idx >= PH * PVD) return;
    int j = idx >> 3, d = idx & 7;
    float s = 0.f;
    for (int k = 0; k < PH; k++)
        s = fmaf(W_hh[j * PH + k], W_sh[k * PVD + d], s);
    g_Wfold[idx] = s;
}

// ---------------------------------------------------------------------------
// GEMM (NT), f32x2 FMAs, conflict-free micro-tile (unchanged from R7).
// ---------------------------------------------------------------------------
__global__ __launch_bounds__(256, 2) void gemm_nt(
    const float* __restrict__ A_in, const float* __restrict__ Bm,
    const float* __restrict__ bias1, const float* __restrict__ bias2,
    float* __restrict__ C_in, int M, int N, int K, int dstXp, int srcH)
{
    const float* A = srcH ? (const float*)g_H : A_in;
    float* C = dstXp ? (float*)g_Xp : C_in;

    __shared__ __align__(16) float As[16][132];
    __shared__ __align__(16) float Bs[16][132];

    const int tid = threadIdx.x;
    const int m0 = blockIdx.x * 128;
    const int n0 = blockIdx.y * 128;

    const int r = tid >> 2;
    const int c = (tid & 3) * 4;

    const float* Ap = A + (size_t)(m0 + r) * K + c;
    const float* Bp = Bm + (size_t)(n0 + r) * K + c;

    const int ty = tid >> 4;
    const int tx = tid & 15;

    unsigned long long acc2[8][4];
    #pragma unroll
    for (int i = 0; i < 8; i++)
        #pragma unroll
        for (int j = 0; j < 4; j++) acc2[i][j] = 0ull;

    for (int k0 = 0; k0 < K; k0 += 16) {
        float4 a0 = *(const float4*)(Ap + k0);
        float4 a1 = *(const float4*)(Ap + k0 + (size_t)64 * K);
        float4 b0 = *(const float4*)(Bp + k0);
        float4 b1 = *(const float4*)(Bp + k0 + (size_t)64 * K);

        __syncthreads();
        As[c+0][r] = a0.x; As[c+1][r] = a0.y; As[c+2][r] = a0.z; As[c+3][r] = a0.w;
        As[c+0][r+64] = a1.x; As[c+1][r+64] = a1.y; As[c+2][r+64] = a1.z; As[c+3][r+64] = a1.w;
        Bs[c+0][r] = b0.x; Bs[c+1][r] = b0.y; Bs[c+2][r] = b0.z; Bs[c+3][r] = b0.w;
        Bs[c+0][r+64] = b1.x; Bs[c+1][r+64] = b1.y; Bs[c+2][r+64] = b1.z; Bs[c+3][r+64] = b1.w;
        __syncthreads();

        #pragma unroll
        for (int kk = 0; kk < 16; kk++) {
            const float4* Arow = (const float4*)&As[kk][0];
            float4 av0 = Arow[ty];
            float4 av1 = Arow[16 + ty];
            const ulonglong2* Brow = (const ulonglong2*)&Bs[kk][0];
            ulonglong2 bp01 = Brow[tx];
            ulonglong2 bp23 = Brow[16 + tx];
            float a_[8] = {av0.x, av0.y, av0.z, av0.w, av1.x, av1.y, av1.z, av1.w};
            #pragma unroll
            for (int i = 0; i < 8; i++) {
                unsigned long long ap;
                PACK2(ap, a_[i], a_[i]);
                FMA2(acc2[i][0], ap, bp01.x, acc2[i][0]);
                FMA2(acc2[i][1], ap, bp01.y, acc2[i][1]);
                FMA2(acc2[i][2], ap, bp23.x, acc2[i][2]);
                FMA2(acc2[i][3], ap, bp23.y, acc2[i][3]);
            }
        }
    }

    const int nb0 = n0 + tx * 4;
    const int nb1 = n0 + 64 + tx * 4;
    float bs0[4], bs1[4];
    #pragma unroll
    for (int j = 0; j < 4; j++) {
        float b0v = 0.f, b1v = 0.f;
        if (bias1) { b0v += bias1[nb0 + j]; b1v += bias1[nb1 + j]; }
        if (bias2) { b0v += bias2[nb0 + j]; b1v += bias2[nb1 + j]; }
        bs0[j] = b0v; bs1[j] = b1v;
    }
    #pragma unroll
    for (int i = 0; i < 8; i++) {
        const int m = m0 + (i < 4 ? ty * 4 + i : 64 + ty * 4 + (i - 4));
        float v[8];
        #pragma unroll
        for (int j4 = 0; j4 < 4; j4++) UNPACK2(v[2*j4], v[2*j4+1], acc2[i][j4]);
        float4 o0 = make_float4(v[0]+bs0[0], v[1]+bs0[1], v[2]+bs0[2], v[3]+bs0[3]);
        float4 o1 = make_float4(v[4]+bs1[0], v[5]+bs1[1], v[6]+bs1[2], v[7]+bs1[3]);
        *(float4*)&C[(size_t)m * N + nb0] = o0;
        *(float4*)&C[(size_t)m * N + nb1] = o1;
    }
}

// ---------------------------------------------------------------------------
// Sequential scan — split-K pipelined. Thread (row jl, slice q) covers
// k in [half*128+32q,+32) (own) and [(1-half)*128+32q,+32) (peer).
// Per step: [own matvec + own dots + prev blend + g_H] || handshake-wait,
// then peer matvec/dots, sync, redundant gate math, tail+tanh+exchange, sync.
// h layout: 8 chunks of 32 floats padded to 36 (conflict-free broadcasts).
// ---------------------------------------------------------------------------
#define CH   36
#define HBUFN (8 * CH)   // 288 floats per h buffer
__device__ __forceinline__ int hidx(int k) { return (k >> 5) * CH + (k & 31); }

__global__ void __cluster_dims__(2, 1, 1) __launch_bounds__(512, 1)
scan_kernel(const float* __restrict__ stack0, const float* __restrict__ hidden0,
            const float* __restrict__ W_hh, const float* __restrict__ W_a,
            const float* __restrict__ W_n, float* __restrict__ out)
{
    __shared__ __align__(16) float sh_h[2][HBUFN];
    __shared__ float sh_stack[2][PD * PVD];
    __shared__ float sh_dots[11];
    __shared__ __align__(8) unsigned long long sh_bar;

    const int tid   = threadIdx.x;
    const int batch = blockIdx.x >> 1;
    const int half  = blockIdx.x & 1;
    const int jl    = tid >> 2;
    const int q     = tid & 3;
    const int jg    = half * 128 + jl;
    const int jgp   = hidx(jg);
    const int wid   = tid >> 5, lane = tid & 31;
    const int own_c0  = half * 4;          // own chunks [own_c0, own_c0+4)
    const int peer_c0 = 4 - own_c0;

    // Register-resident W_hh: own 32 k + peer 32 k (16 f32x2 pairs each)
    unsigned long long wpo[16], wpp[16];
    {
        const float* wrow = W_hh + (size_t)jg * PH;
        const unsigned long long* wo = (const unsigned long long*)(wrow + half * 128 + 32 * q);
        const unsigned long long* wpr = (const unsigned long long*)(wrow + (1 - half) * 128 + 32 * q);
        #pragma unroll
        for (int i = 0; i < 16; i++) { wpo[i] = wo[i]; wpp[i] = wpr[i]; }
    }
    const float wf0 = g_Wfold[jg * PVD + 2 * q];
    const float wf1 = g_Wfold[jg * PVD + 2 * q + 1];

    // Gate weights in registers (warps 0..10): wan[i] ~ k = lane + 32*i
    float wan[8];
    {
        const float* wr = (wid < 3) ? (W_a + wid * PH)
                        : (W_n + ((wid < 11 ? wid : 3) - 3) * PH);
        #pragma unroll
        for (int i = 0; i < 8; i++) wan[i] = wr[lane + 32 * i];
    }

    if (tid < PH) sh_h[0][hidx(tid)] = hidden0[batch * PH + tid];
    for (int e = tid; e < PD * PVD; e += 512) sh_stack[0][e] = stack0[batch * PD * PVD + e];

    const uint32_t h_u32   = s2u(&sh_h[0][0]);
    const uint32_t bar_u32 = s2u(&sh_bar);
    uint32_t peer_h, peer_bar;
    const uint32_t prank = (uint32_t)(half ^ 1);
    asm("mapa.shared::cluster.u32 %0, %1, %2;" : "=r"(peer_h)   : "r"(h_u32),   "r"(prank));
    asm("mapa.shared::cluster.u32 %0, %1, %2;" : "=r"(peer_bar) : "r"(bar_u32), "r"(prank));

    if (tid == 0)
        asm volatile("mbarrier.init.shared.b64 [%0], 1;" :: "r"(bar_u32) : "memory");

    float xp_cur = 0.f;
    if (q == 0) xp_cur = g_Xp[((size_t)batch * PT) * PH + jg];

    __syncthreads();
    asm volatile("barrier.cluster.arrive.aligned;" ::: "memory");
    asm volatile("barrier.cluster.wait.aligned;"   ::: "memory");

    // Gates(h_{t-1}) carried in registers for the deferred blend
    float ga0 = 0.f, ga1 = 0.f, ga2 = 1.f, gnb = 0.f;

    for (int t = 0; t < PT; t++) {
        const int buf  = t & 1;
        const int nbuf = buf ^ 1;

        float xp_next = 0.f;
        if (q == 0 && t + 1 < PT)
            xp_next = g_Xp[((size_t)batch * PT + t + 1) * PH + jg];

        // ================= OWN PHASE (no peer data needed) =================
        unsigned long long a0 = 0ull, a1 = 0ull, a2 = 0ull, a3 = 0ull;
        {
            const ulonglong2* hv = (const ulonglong2*)&sh_h[buf][(own_c0 + q) * CH];
            #pragma unroll
            for (int i = 0; i < 8; i++) {
                ulonglong2 h = hv[i];
                FMA2(a0, wpo[2*i],   h.x, a0);
                FMA2(a1, wpo[2*i+1], h.y, a1);
            }
        }
        float pdot = 0.f;
        if (wid < 11) {
            #pragma unroll
            for (int i = 0; i < 4; i++)
                pdot = fmaf(sh_h[buf][(own_c0 + i) * CH + lane], wan[own_c0 + i], pdot);
        } else if (wid >= 12 && t > 0) {
            const int i = tid - 384;   // 0..127
            g_H[((size_t)batch * PT + t - 1) * PH + half * 128 + i] =
                sh_h[buf][hidx(half * 128 + i)];
        }
        // deferred stack blend with gates(h_{t-1}): S[nbuf] -> S[buf]
        if (t > 0) {
            #pragma unroll
            for (int rr = 0; rr < 2; rr++) {
                const int e = tid + rr * 512;
                const int p = e >> 3;
                const float push = (p == 0)      ? gnb : sh_stack[nbuf][e - 8];
                const float pop  = (p == PD - 1) ? 0.f : sh_stack[nbuf][e + 8];
                sh_stack[buf][e] = ga0 * push + ga1 * pop + ga2 * sh_stack[nbuf][e];
            }
        }

        // ================= WAIT for peer half of h_t =======================
        if (t > 0) {
            const uint32_t par = (uint32_t)((t - 1) & 1);
            uint32_t done;
            do {
                asm volatile("{\n\t.reg .pred P;\n\t"
                    "mbarrier.try_wait.parity.acquire.cluster.shared::cta.b64 P, [%1], %2, 0x989680;\n\t"
                    "selp.b32 %0, 1, 0, P;\n\t}"
                    : "=r"(done) : "r"(bar_u32), "r"(par) : "memory");
            } while (!done);
        }

        // ================= PEER PHASE ======================================
        {
            const ulonglong2* hv = (const ulonglong2*)&sh_h[buf][(peer_c0 + q) * CH];
            #pragma unroll
            for (int i = 0; i < 8; i++) {
                ulonglong2 h = hv[i];
                FMA2(a2, wpp[2*i],   h.x, a2);
                FMA2(a3, wpp[2*i+1], h.y, a3);
            }
        }
        if (wid < 11) {
            #pragma unroll
            for (int i = 0; i < 4; i++)
                pdot = fmaf(sh_h[buf][(peer_c0 + i) * CH + lane], wan[peer_c0 + i], pdot);
            #pragma unroll
            for (int o = 16; o > 0; o >>= 1)
                pdot += __shfl_xor_sync(0xffffffffu, pdot, o);
            if (lane == 0) sh_dots[wid] = pdot;
        }
        __syncthreads();                       // sync1: sh_dots + blend visible

        // ======= GATES (redundant, per-thread) + tail + tanh + exchange ====
        float A0, A1, A2, n0, n1;
        if (t == 0) {
            A0 = 0.f; A1 = 0.f; A2 = 1.f; n0 = 0.f; n1 = 0.f; gnb = 0.f;
        } else {
            const float d0 = sh_dots[0], d1 = sh_dots[1], d2 = sh_dots[2];
            const float mx = fmaxf(d0, fmaxf(d1, d2));
            const float e0 = __expf(d0 - mx), e1 = __expf(d1 - mx), e2 = __expf(d2 - mx);
            const float inv = __fdividef(1.f, e0 + e1 + e2);
            A0 = e0 * inv; A1 = e1 * inv; A2 = e2 * inv;
            n0 = fast_sigmoid(sh_dots[3 + 2 * q]);
            n1 = fast_sigmoid(sh_dots[3 + 2 * q + 1]);
            gnb = (tid < PVD) ? fast_sigmoid(sh_dots[3 + tid]) : 0.f;
        }
        ga0 = A0; ga1 = A1; ga2 = A2;

        ADD2(a0, a0, a1); ADD2(a2, a2, a3); ADD2(a0, a0, a2);
        float lo, hi; UNPACK2(lo, hi, a0);
        float acc = lo + hi;
        {
            const float s_t0 = sh_stack[buf][2 * q],     s_t1 = sh_stack[buf][2 * q + 1];
            const float s_b0 = sh_stack[buf][8 + 2 * q], s_b1 = sh_stack[buf][8 + 2 * q + 1];
            const float top0 = A0 * n0 + A1 * s_b0 + A2 * s_t0;
            const float top1 = A0 * n1 + A1 * s_b1 + A2 * s_t1;
            acc = fmaf(wf0, top0, acc);
            acc = fmaf(wf1, top1, acc);
        }
        acc += __shfl_xor_sync(0xffffffffu, acc, 1);
        acc += __shfl_xor_sync(0xffffffffu, acc, 2);
        if (q == 0) {
            const float hn = fast_tanh(acc + xp_cur);
            sh_h[nbuf][jgp] = hn;
            asm volatile("st.shared::cluster.f32 [%0], %1;"
                         :: "r"(peer_h + (uint32_t)((nbuf * HBUFN + jgp) * 4)), "f"(hn)
                         : "memory");
        }
        xp_cur = xp_next;
        __syncthreads();                       // sync2: local h stores visible

        if (tid == 0)
            asm volatile("mbarrier.arrive.release.cluster.shared::cluster.b64 _, [%0];"
                         :: "r"(peer_bar) : "memory");
    }

    // ===================== EPILOGUE ========================================
    {   // wait for peer half of h_PT
        const uint32_t par = (uint32_t)((PT - 1) & 1);
        uint32_t done;
        do {
            asm volatile("{\n\t.reg .pred P;\n\t"
                "mbarrier.try_wait.parity.acquire.cluster.shared::cta.b64 P, [%1], %2, 0x989680;\n\t"
                "selp.b32 %0, 1, 0, P;\n\t}"
                : "=r"(done) : "r"(bar_u32), "r"(par) : "memory");
        } while (!done);
    }
    // pending blend with gates(h_{PT-1}): S[1] -> S[0]  (= stack_{PT-1})
    #pragma unroll
    for (int rr = 0; rr < 2; rr++) {
        const int e = tid + rr * 512;
        const int p = e >> 3;
        const float push = (p == 0)      ? gnb : sh_stack[1][e - 8];
        const float pop  = (p == PD - 1) ? 0.f : sh_stack[1][e + 8];
        sh_stack[0][e] = ga0 * push + ga1 * pop + ga2 * sh_stack[1][e];
    }
    __syncthreads();
    // dots(h_PT) (h_PT lives in sh_h[0], full after the wait)
    if (wid < 11) {
        float p = 0.f;
        #pragma unroll
        for (int i = 0; i < 8; i++)
            p = fmaf(sh_h[0][i * CH + lane], wan[i], p);
        #pragma unroll
        for (int o = 16; o > 0; o >>= 1)
            p += __shfl_xor_sync(0xffffffffu, p, o);
        if (lane == 0) sh_dots[wid] = p;
    } else if (wid >= 12) {
        const int i = tid - 384;
        g_H[((size_t)batch * PT + PT - 1) * PH + half * 128 + i] =
            sh_h[0][hidx(half * 128 + i)];
    }
    __syncthreads();
    {   // final gates + blend: S[0] -> S[1] (= stack_PT)
        const float d0 = sh_dots[0], d1 = sh_dots[1], d2 = sh_dots[2];
        const float mx = fmaxf(d0, fmaxf(d1, d2));
        const float e0 = __expf(d0 - mx), e1 = __expf(d1 - mx), e2 = __expf(d2 - mx);
        const float inv = __fdividef(1.f, e0 + e1 + e2);
        const float A0 = e0 * inv, A1 = e1 * inv, A2 = e2 * inv;
        const float nb = (tid < PVD) ? fast_sigmoid(sh_dots[3 + tid]) : 0.f;
        __syncthreads();
        #pragma unroll
        for (int rr = 0; rr < 2; rr++) {
            const int e = tid + rr * 512;
            const int p = e >> 3;
            const float push = (p == 0)      ? nb  : sh_stack[0][e - 8];
            const float pop  = (p == PD - 1) ? 0.f : sh_stack[0][e + 8];
            sh_stack[1][e] = A0 * push + A1 * pop + A2 * sh_stack[0][e];
        }
    }
    __syncthreads();

    const size_t OUT_Y = (size_t)PB * PT * PV;
    if (half == 0) {
        for (int e = tid; e < PD * PVD; e += 512)
            out[OUT_Y + (size_t)batch * PD * PVD + e] = sh_stack[1][e];
    }
    if (tid < 128) {
        const int row = half * 128 + tid;
        out[OUT_Y + (size_t)PB * PD * PVD + (size_t)batch * PH + row] =
            sh_h[0][hidx(row)];
    }

    asm volatile("barrier.cluster.arrive.aligned;" ::: "memory");
    asm volatile("barrier.cluster.wait.aligned;"   ::: "memory");
}

// ---------------------------------------------------------------------------
extern "C" void kernel_launch(void* const* d_in, const int* in_sizes, int n_in,
                              void* d_out, int out_size)
{
    const float* inputs  = (const float*)d_in[0];
    const float* stack0  = (const float*)d_in[1];
    const float* hidden0 = (const float*)d_in[2];
    const float* W_ih    = (const float*)d_in[3];
    const float* b_ih    = (const float*)d_in[4];
    const float* W_hh    = (const float*)d_in[5];
    const float* b_hh    = (const float*)d_in[6];
    const float* W_sh    = (const float*)d_in[7];
    const float* W_y     = (const float*)d_in[8];
    const float* W_a     = (const float*)d_in[9];
    const float* W_n     = (const float*)d_in[10];
    float* out = (float*)d_out;

    const int M = PB * PT;  // 131072

    fold_kernel<<<8, 256>>>(W_hh, W_sh);
    gemm_nt<<<dim3(M / 128, PH / 128), 256>>>(inputs, W_ih, b_ih, b_hh,
                                              nullptr, M, PH, PV, 1, 0);
    scan_kernel<<<2 * PB, 512>>>(stack0, hidden0, W_hh, W_a, W_n, out);
    gemm_nt<<<dim3(M / 128, PV / 128), 256>>>(nullptr, W_y, nullptr, nullptr,
                                              out, M, PV, PH, 0, 1);
}

// round 9
// speedup vs baseline: 1.5513x; 1.5513x over previous
#include <cuda_runtime.h>
#include <cuda_bf16.h>
#include <math.h>
#include <stdint.h>

// Problem constants
#define PB   64
#define PT   2048
#define PH   256
#define PV   512
#define PVD  8
#define PD   128

// Scratch
__device__ float g_Xp[(size_t)PB * PT * PH];   // inputs @ W_ih.T + b
__device__ float g_H [(size_t)PB * PT * PH];   // hidden states
__device__ float g_Wfold[PH * PVD];            // W_hh @ W_sh  (256 x 8)

// ---- f32x2 packed-FMA helpers (sm_103a FFMA2) ------------------------------
#define FMA2(d,a,b,c) asm("fma.rn.f32x2 %0, %1, %2, %3;" : "=l"(d) : "l"(a), "l"(b), "l"(c))
#define ADD2(d,a,b)   asm("add.rn.f32x2 %0, %1, %2;"     : "=l"(d) : "l"(a), "l"(b))
#define PACK2(d,lo,hi) asm("mov.b64 %0, {%1, %2};" : "=l"(d) : "r"(__float_as_uint(lo)), "r"(__float_as_uint(hi)))
#define UNPACK2(lo,hi,s) do { unsigned _ulo, _uhi; \
    asm("mov.b64 {%0, %1}, %2;" : "=r"(_ulo), "=r"(_uhi) : "l"(s)); \
    lo = __uint_as_float(_ulo); hi = __uint_as_float(_uhi); } while (0)

__device__ __forceinline__ uint32_t s2u(const void* p) {
    uint32_t a;
    asm("{ .reg .u64 t; cvta.to.shared.u64 t, %1; cvt.u32.u64 %0, t; }" : "=r"(a) : "l"(p));
    return a;
}

__device__ __forceinline__ float fast_tanh(float x) {
    const float xc = fminf(fmaxf(x, -10.f), 10.f);
    const float e = __expf(2.f * xc);
    return __fdividef(e - 1.f, e + 1.f);
}
__device__ __forceinline__ float fast_sigmoid(float x) {
    return __fdividef(1.f, 1.f + __expf(-x));
}

// ---------------------------------------------------------------------------
__global__ void fold_kernel(const float* __restrict__ W_hh,
                            const float* __restrict__ W_sh)
{
    int idx = blockIdx.x * blockDim.x + threadIdx.x;
    if (idx >= PH * PVD) return;
    int j = idx >> 3, d = idx & 7;
    float s = 0.f;
    for (int k = 0; k < PH; k++)
        s = fmaf(W_hh[j * PH + k], W_sh[k * PVD + d], s);
    g_Wfold[idx] = s;
}

// ---------------------------------------------------------------------------
// GEMM (NT), f32x2 FMAs, DOUBLE-BUFFERED smem: one syncthreads per k-tile,
// tile i+1 LDGs issued before/mid compute of tile i (latency hidden).
// ---------------------------------------------------------------------------
#define GEMM_HALF(curbuf, base)                                               \
    _Pragma("unroll")                                                         \
    for (int kk = (base); kk < (base) + 8; kk++) {                            \
        const float4* Arow = (const float4*)&As[curbuf][kk][0];               \
        float4 av0 = Arow[ty];                                                \
        float4 av1 = Arow[16 + ty];                                           \
        const ulonglong2* Brow = (const ulonglong2*)&Bs[curbuf][kk][0];       \
        ulonglong2 bp01 = Brow[tx];                                           \
        ulonglong2 bp23 = Brow[16 + tx];                                      \
        float a_[8] = {av0.x, av0.y, av0.z, av0.w, av1.x, av1.y, av1.z, av1.w};\
        _Pragma("unroll")                                                     \
        for (int i = 0; i < 8; i++) {                                         \
            unsigned long long ap;                                            \
            PACK2(ap, a_[i], a_[i]);                                          \
            FMA2(acc2[i][0], ap, bp01.x, acc2[i][0]);                         \
            FMA2(acc2[i][1], ap, bp01.y, acc2[i][1]);                         \
            FMA2(acc2[i][2], ap, bp23.x, acc2[i][2]);                         \
            FMA2(acc2[i][3], ap, bp23.y, acc2[i][3]);                         \
        }                                                                     \
    }

__global__ __launch_bounds__(256, 2) void gemm_nt(
    const float* __restrict__ A_in, const float* __restrict__ Bm,
    const float* __restrict__ bias1, const float* __restrict__ bias2,
    float* __restrict__ C_in, int M, int N, int K, int dstXp, int srcH)
{
    const float* A = srcH ? (const float*)g_H : A_in;
    float* C = dstXp ? (float*)g_Xp : C_in;

    __shared__ __align__(16) float As[2][16][132];
    __shared__ __align__(16) float Bs[2][16][132];

    const int tid = threadIdx.x;
    const int m0 = blockIdx.x * 128;
    const int n0 = blockIdx.y * 128;

    const int r = tid >> 2;
    const int c = (tid & 3) * 4;

    const float* Ap = A + (size_t)(m0 + r) * K + c;
    const float* Bp = Bm + (size_t)(n0 + r) * K + c;

    const int ty = tid >> 4;
    const int tx = tid & 15;

    unsigned long long acc2[8][4];
    #pragma unroll
    for (int i = 0; i < 8; i++)
        #pragma unroll
        for (int j = 0; j < 4; j++) acc2[i][j] = 0ull;

    // prologue: tile 0 -> buf 0
    {
        float4 a0 = *(const float4*)(Ap);
        float4 a1 = *(const float4*)(Ap + (size_t)64 * K);
        float4 b0 = *(const float4*)(Bp);
        float4 b1 = *(const float4*)(Bp + (size_t)64 * K);
        As[0][c+0][r] = a0.x; As[0][c+1][r] = a0.y; As[0][c+2][r] = a0.z; As[0][c+3][r] = a0.w;
        As[0][c+0][r+64] = a1.x; As[0][c+1][r+64] = a1.y; As[0][c+2][r+64] = a1.z; As[0][c+3][r+64] = a1.w;
        Bs[0][c+0][r] = b0.x; Bs[0][c+1][r] = b0.y; Bs[0][c+2][r] = b0.z; Bs[0][c+3][r] = b0.w;
        Bs[0][c+0][r+64] = b1.x; Bs[0][c+1][r+64] = b1.y; Bs[0][c+2][r+64] = b1.z; Bs[0][c+3][r+64] = b1.w;
    }
    __syncthreads();

    const int NT = K / 16;
    for (int it = 0; it < NT; it++) {
        const int cur = it & 1;
        const int nxt = cur ^ 1;
        const bool more = (it + 1 < NT);
        const int ko = (it + 1) * 16;

        float4 na0, nb0;
        if (more) {
            na0 = *(const float4*)(Ap + ko);
            nb0 = *(const float4*)(Bp + ko);
        }

        GEMM_HALF(cur, 0)

        float4 na1, nb1;
        if (more) {
            As[nxt][c+0][r] = na0.x; As[nxt][c+1][r] = na0.y;
            As[nxt][c+2][r] = na0.z; As[nxt][c+3][r] = na0.w;
            Bs[nxt][c+0][r] = nb0.x; Bs[nxt][c+1][r] = nb0.y;
            Bs[nxt][c+2][r] = nb0.z; Bs[nxt][c+3][r] = nb0.w;
            na1 = *(const float4*)(Ap + ko + (size_t)64 * K);
            nb1 = *(const float4*)(Bp + ko + (size_t)64 * K);
        }

        GEMM_HALF(cur, 8)

        if (more) {
            As[nxt][c+0][r+64] = na1.x; As[nxt][c+1][r+64] = na1.y;
            As[nxt][c+2][r+64] = na1.z; As[nxt][c+3][r+64] = na1.w;
            Bs[nxt][c+0][r+64] = nb1.x; Bs[nxt][c+1][r+64] = nb1.y;
            Bs[nxt][c+2][r+64] = nb1.z; Bs[nxt][c+3][r+64] = nb1.w;
        }
        __syncthreads();
    }

    const int nb0i = n0 + tx * 4;
    const int nb1i = n0 + 64 + tx * 4;
    float bs0[4], bs1[4];
    #pragma unroll
    for (int j = 0; j < 4; j++) {
        float b0v = 0.f, b1v = 0.f;
        if (bias1) { b0v += bias1[nb0i + j]; b1v += bias1[nb1i + j]; }
        if (bias2) { b0v += bias2[nb0i + j]; b1v += bias2[nb1i + j]; }
        bs0[j] = b0v; bs1[j] = b1v;
    }
    #pragma unroll
    for (int i = 0; i < 8; i++) {
        const int m = m0 + (i < 4 ? ty * 4 + i : 64 + ty * 4 + (i - 4));
        float v[8];
        #pragma unroll
        for (int j4 = 0; j4 < 4; j4++) UNPACK2(v[2*j4], v[2*j4+1], acc2[i][j4]);
        float4 o0 = make_float4(v[0]+bs0[0], v[1]+bs0[1], v[2]+bs0[2], v[3]+bs0[3]);
        float4 o1 = make_float4(v[4]+bs1[0], v[5]+bs1[1], v[6]+bs1[2], v[7]+bs1[3]);
        *(float4*)&C[(size_t)m * N + nb0i] = o0;
        *(float4*)&C[(size_t)m * N + nb1i] = o1;
    }
}

// ---------------------------------------------------------------------------
// Sequential scan — split-K pipelined (R8 structure) with LANE-SPLIT gates:
// one __expf per warp covers all 11 exponentials; results shfl-broadcast.
// ---------------------------------------------------------------------------
#define CH   36
#define HBUFN (8 * CH)
__device__ __forceinline__ int hidx(int k) { return (k >> 5) * CH + (k & 31); }

__global__ void __cluster_dims__(2, 1, 1) __launch_bounds__(512, 1)
scan_kernel(const float* __restrict__ stack0, const float* __restrict__ hidden0,
            const float* __restrict__ W_hh, const float* __restrict__ W_a,
            const float* __restrict__ W_n, float* __restrict__ out)
{
    __shared__ __align__(16) float sh_h[2][HBUFN];
    __shared__ float sh_stack[2][PD * PVD];
    __shared__ float sh_dots[11];
    __shared__ __align__(8) unsigned long long sh_bar;

    const int tid   = threadIdx.x;
    const int batch = blockIdx.x >> 1;
    const int half  = blockIdx.x & 1;
    const int jl    = tid >> 2;
    const int q     = tid & 3;
    const int jg    = half * 128 + jl;
    const int jgp   = hidx(jg);
    const int wid   = tid >> 5, lane = tid & 31;
    const int own_c0  = half * 4;
    const int peer_c0 = 4 - own_c0;

    unsigned long long wpo[16], wpp[16];
    {
        const float* wrow = W_hh + (size_t)jg * PH;
        const unsigned long long* wo = (const unsigned long long*)(wrow + half * 128 + 32 * q);
        const unsigned long long* wpr = (const unsigned long long*)(wrow + (1 - half) * 128 + 32 * q);
        #pragma unroll
        for (int i = 0; i < 16; i++) { wpo[i] = wo[i]; wpp[i] = wpr[i]; }
    }
    const float wf0 = g_Wfold[jg * PVD + 2 * q];
    const float wf1 = g_Wfold[jg * PVD + 2 * q + 1];

    float wan[8];
    {
        const float* wr = (wid < 3) ? (W_a + wid * PH)
                        : (W_n + ((wid < 11 ? wid : 3) - 3) * PH);
        #pragma unroll
        for (int i = 0; i < 8; i++) wan[i] = wr[lane + 32 * i];
    }

    if (tid < PH) sh_h[0][hidx(tid)] = hidden0[batch * PH + tid];
    for (int e = tid; e < PD * PVD; e += 512) sh_stack[0][e] = stack0[batch * PD * PVD + e];

    const uint32_t h_u32   = s2u(&sh_h[0][0]);
    const uint32_t bar_u32 = s2u(&sh_bar);
    uint32_t peer_h, peer_bar;
    const uint32_t prank = (uint32_t)(half ^ 1);
    asm("mapa.shared::cluster.u32 %0, %1, %2;" : "=r"(peer_h)   : "r"(h_u32),   "r"(prank));
    asm("mapa.shared::cluster.u32 %0, %1, %2;" : "=r"(peer_bar) : "r"(bar_u32), "r"(prank));

    if (tid == 0)
        asm volatile("mbarrier.init.shared.b64 [%0], 1;" :: "r"(bar_u32) : "memory");

    float xp_cur = 0.f;
    if (q == 0) xp_cur = g_Xp[((size_t)batch * PT) * PH + jg];

    __syncthreads();
    asm volatile("barrier.cluster.arrive.aligned;" ::: "memory");
    asm volatile("barrier.cluster.wait.aligned;"   ::: "memory");

    float ga0 = 0.f, ga1 = 0.f, ga2 = 1.f, gnb = 0.f;

    for (int t = 0; t < PT; t++) {
        const int buf  = t & 1;
        const int nbuf = buf ^ 1;

        float xp_next = 0.f;
        if (q == 0 && t + 1 < PT)
            xp_next = g_Xp[((size_t)batch * PT + t + 1) * PH + jg];

        // ================= OWN PHASE =======================================
        unsigned long long a0 = 0ull, a1 = 0ull, a2 = 0ull, a3 = 0ull;
        {
            const ulonglong2* hv = (const ulonglong2*)&sh_h[buf][(own_c0 + q) * CH];
            #pragma unroll
            for (int i = 0; i < 8; i++) {
                ulonglong2 h = hv[i];
                FMA2(a0, wpo[2*i],   h.x, a0);
                FMA2(a1, wpo[2*i+1], h.y, a1);
            }
        }
        float pdot = 0.f;
        if (wid < 11) {
            #pragma unroll
            for (int i = 0; i < 4; i++)
                pdot = fmaf(sh_h[buf][(own_c0 + i) * CH + lane], wan[own_c0 + i], pdot);
        } else if (wid >= 12 && t > 0) {
            const int i = tid - 384;
            g_H[((size_t)batch * PT + t - 1) * PH + half * 128 + i] =
                sh_h[buf][hidx(half * 128 + i)];
        }
        if (t > 0) {
            #pragma unroll
            for (int rr = 0; rr < 2; rr++) {
                const int e = tid + rr * 512;
                const int p = e >> 3;
                const float push = (p == 0)      ? gnb : sh_stack[nbuf][e - 8];
                const float pop  = (p == PD - 1) ? 0.f : sh_stack[nbuf][e + 8];
                sh_stack[buf][e] = ga0 * push + ga1 * pop + ga2 * sh_stack[nbuf][e];
            }
        }

        // ================= WAIT for peer half of h_t =======================
        if (t > 0) {
            const uint32_t par = (uint32_t)((t - 1) & 1);
            uint32_t done;
            do {
                asm volatile("{\n\t.reg .pred P;\n\t"
                    "mbarrier.try_wait.parity.acquire.cluster.shared::cta.b64 P, [%1], %2, 0x989680;\n\t"
                    "selp.b32 %0, 1, 0, P;\n\t}"
                    : "=r"(done) : "r"(bar_u32), "r"(par) : "memory");
            } while (!done);
        }

        // ================= PEER PHASE ======================================
        {
            const ulonglong2* hv = (const ulonglong2*)&sh_h[buf][(peer_c0 + q) * CH];
            #pragma unroll
            for (int i = 0; i < 8; i++) {
                ulonglong2 h = hv[i];
                FMA2(a2, wpp[2*i],   h.x, a2);
                FMA2(a3, wpp[2*i+1], h.y, a3);
            }
        }
        if (wid < 11) {
            #pragma unroll
            for (int i = 0; i < 4; i++)
                pdot = fmaf(sh_h[buf][(peer_c0 + i) * CH + lane], wan[peer_c0 + i], pdot);
            #pragma unroll
            for (int o = 16; o > 0; o >>= 1)
                pdot += __shfl_xor_sync(0xffffffffu, pdot, o);
            if (lane == 0) sh_dots[wid] = pdot;
        }
        __syncthreads();                       // sync1

        // ======= GATES: lane-split (1 EX2 + 2 RCP per warp) ================
        float A0, A1, A2, n0, n1;
        if (t == 0) {
            A0 = 0.f; A1 = 0.f; A2 = 1.f; n0 = 0.f; n1 = 0.f; gnb = 0.f;
        } else {
            const float d0 = sh_dots[0], d1 = sh_dots[1], d2 = sh_dots[2];
            const float mx = fmaxf(d0, fmaxf(d1, d2));
            float arg;
            if (lane == 0)      arg = d0 - mx;
            else if (lane == 1) arg = d1 - mx;
            else if (lane == 2) arg = d2 - mx;
            else if (lane < 11) arg = -sh_dots[lane];
            else                arg = 0.f;
            const float e   = __expf(arg);
            const float sig = __fdividef(1.f, 1.f + e);   // lanes 3..10 valid
            const float e0 = __shfl_sync(0xffffffffu, e, 0);
            const float e1 = __shfl_sync(0xffffffffu, e, 1);
            const float e2 = __shfl_sync(0xffffffffu, e, 2);
            const float inv = __fdividef(1.f, e0 + e1 + e2);
            A0 = e0 * inv; A1 = e1 * inv; A2 = e2 * inv;
            n0 = __shfl_sync(0xffffffffu, sig, 3 + 2 * q);
            n1 = __shfl_sync(0xffffffffu, sig, 3 + 2 * q + 1);
            gnb = __shfl_sync(0xffffffffu, sig, 3 + (lane & 7));
        }
        ga0 = A0; ga1 = A1; ga2 = A2;

        ADD2(a0, a0, a1); ADD2(a2, a2, a3); ADD2(a0, a0, a2);
        float lo, hi; UNPACK2(lo, hi, a0);
        float acc = lo + hi;
        {
            const float s_t0 = sh_stack[buf][2 * q],     s_t1 = sh_stack[buf][2 * q + 1];
            const float s_b0 = sh_stack[buf][8 + 2 * q], s_b1 = sh_stack[buf][8 + 2 * q + 1];
            const float top0 = A0 * n0 + A1 * s_b0 + A2 * s_t0;
            const float top1 = A0 * n1 + A1 * s_b1 + A2 * s_t1;
            acc = fmaf(wf0, top0, acc);
            acc = fmaf(wf1, top1, acc);
        }
        acc += __shfl_xor_sync(0xffffffffu, acc, 1);
        acc += __shfl_xor_sync(0xffffffffu, acc, 2);
        if (q == 0) {
            const float hn = fast_tanh(acc + xp_cur);
            sh_h[nbuf][jgp] = hn;
            asm volatile("st.shared::cluster.f32 [%0], %1;"
                         :: "r"(peer_h + (uint32_t)((nbuf * HBUFN + jgp) * 4)), "f"(hn)
                         : "memory");
        }
        xp_cur = xp_next;
        __syncthreads();                       // sync2

        if (tid == 0)
            asm volatile("mbarrier.arrive.release.cluster.shared::cluster.b64 _, [%0];"
                         :: "r"(peer_bar) : "memory");
    }

    // ===================== EPILOGUE ========================================
    {
        const uint32_t par = (uint32_t)((PT - 1) & 1);
        uint32_t done;
        do {
            asm volatile("{\n\t.reg .pred P;\n\t"
                "mbarrier.try_wait.parity.acquire.cluster.shared::cta.b64 P, [%1], %2, 0x989680;\n\t"
                "selp.b32 %0, 1, 0, P;\n\t}"
                : "=r"(done) : "r"(bar_u32), "r"(par) : "memory");
        } while (!done);
    }
    #pragma unroll
    for (int rr = 0; rr < 2; rr++) {
        const int e = tid + rr * 512;
        const int p = e >> 3;
        const float push = (p == 0)      ? gnb : sh_stack[1][e - 8];
        const float pop  = (p == PD - 1) ? 0.f : sh_stack[1][e + 8];
        sh_stack[0][e] = ga0 * push + ga1 * pop + ga2 * sh_stack[1][e];
    }
    __syncthreads();
    if (wid < 11) {
        float p = 0.f;
        #pragma unroll
        for (int i = 0; i < 8; i++)
            p = fmaf(sh_h[0][i * CH + lane], wan[i], p);
        #pragma unroll
        for (int o = 16; o > 0; o >>= 1)
            p += __shfl_xor_sync(0xffffffffu, p, o);
        if (lane == 0) sh_dots[wid] = p;
    } else if (wid >= 12) {
        const int i = tid - 384;
        g_H[((size_t)batch * PT + PT - 1) * PH + half * 128 + i] =
            sh_h[0][hidx(half * 128 + i)];
    }
    __syncthreads();
    {
        const float d0 = sh_dots[0], d1 = sh_dots[1], d2 = sh_dots[2];
        const float mx = fmaxf(d0, fmaxf(d1, d2));
        const float e0 = __expf(d0 - mx), e1 = __expf(d1 - mx), e2 = __expf(d2 - mx);
        const float inv = __fdividef(1.f, e0 + e1 + e2);
        const float A0 = e0 * inv, A1 = e1 * inv, A2 = e2 * inv;
        const float nb = (tid < PVD) ? fast_sigmoid(sh_dots[3 + tid]) : 0.f;
        __syncthreads();
        #pragma unroll
        for (int rr = 0; rr < 2; rr++) {
            const int e = tid + rr * 512;
            const int p = e >> 3;
            const float push = (p == 0)      ? nb  : sh_stack[0][e - 8];
            const float pop  = (p == PD - 1) ? 0.f : sh_stack[0][e + 8];
            sh_stack[1][e] = A0 * push + A1 * pop + A2 * sh_stack[0][e];
        }
    }
    __syncthreads();

    const size_t OUT_Y = (size_t)PB * PT * PV;
    if (half == 0) {
        for (int e = tid; e < PD * PVD; e += 512)
            out[OUT_Y + (size_t)batch * PD * PVD + e] = sh_stack[1][e];
    }
    if (tid < 128) {
        const int row = half * 128 + tid;
        out[OUT_Y + (size_t)PB * PD * PVD + (size_t)batch * PH + row] =
            sh_h[0][hidx(row)];
    }

    asm volatile("barrier.cluster.arrive.aligned;" ::: "memory");
    asm volatile("barrier.cluster.wait.aligned;"   ::: "memory");
}

// ---------------------------------------------------------------------------
extern "C" void kernel_launch(void* const* d_in, const int* in_sizes, int n_in,
                              void* d_out, int out_size)
{
    const float* inputs  = (const float*)d_in[0];
    const float* stack0  = (const float*)d_in[1];
    const float* hidden0 = (const float*)d_in[2];
    const float* W_ih    = (const float*)d_in[3];
    const float* b_ih    = (const float*)d_in[4];
    const float* W_hh    = (const float*)d_in[5];
    const float* b_hh    = (const float*)d_in[6];
    const float* W_sh    = (const float*)d_in[7];
    const float* W_y     = (const float*)d_in[8];
    const float* W_a     = (const float*)d_in[9];
    const float* W_n     = (const float*)d_in[10];
    float* out = (float*)d_out;

    const int M = PB * PT;  // 131072

    fold_kernel<<<8, 256>>>(W_hh, W_sh);
    gemm_nt<<<dim3(M / 128, PH / 128), 256>>>(inputs, W_ih, b_ih, b_hh,
                                              nullptr, M, PH, PV, 1, 0);
    scan_kernel<<<2 * PB, 512>>>(stack0, hidden0, W_hh, W_a, W_n, out);
    gemm_nt<<<dim3(M / 128, PV / 128), 256>>>(nullptr, W_y, nullptr, nullptr,
                                              out, M, PV, PH, 0, 1);
}

// round 10
// speedup vs baseline: 1.6373x; 1.0554x over previous
#include <cuda_runtime.h>
#include <cuda_bf16.h>
#include <math.h>
#include <stdint.h>

// Problem constants
#define PB   64
#define PT   2048
#define PH   256
#define PV   512
#define PVD  8
#define PD   128

// Scratch
__device__ float g_Xp[(size_t)PB * PT * PH];   // inputs @ W_ih.T + b
__device__ float g_H [(size_t)PB * PT * PH];   // hidden states
__device__ float g_Wfold[PH * PVD];            // W_hh @ W_sh  (256 x 8)

// ---- f32x2 packed-FMA helpers (sm_103a FFMA2) ------------------------------
#define FMA2(d,a,b,c) asm("fma.rn.f32x2 %0, %1, %2, %3;" : "=l"(d) : "l"(a), "l"(b), "l"(c))
#define ADD2(d,a,b)   asm("add.rn.f32x2 %0, %1, %2;"     : "=l"(d) : "l"(a), "l"(b))
#define PACK2(d,lo,hi) asm("mov.b64 %0, {%1, %2};" : "=l"(d) : "r"(__float_as_uint(lo)), "r"(__float_as_uint(hi)))
#define UNPACK2(lo,hi,s) do { unsigned _ulo, _uhi; \
    asm("mov.b64 {%0, %1}, %2;" : "=r"(_ulo), "=r"(_uhi) : "l"(s)); \
    lo = __uint_as_float(_ulo); hi = __uint_as_float(_uhi); } while (0)

__device__ __forceinline__ uint32_t s2u(const void* p) {
    uint32_t a;
    asm("{ .reg .u64 t; cvta.to.shared.u64 t, %1; cvt.u32.u64 %0, t; }" : "=r"(a) : "l"(p));
    return a;
}

__device__ __forceinline__ float fast_tanh(float x) {
    const float xc = fminf(fmaxf(x, -10.f), 10.f);
    const float e = __expf(2.f * xc);
    return __fdividef(e - 1.f, e + 1.f);
}
__device__ __forceinline__ float fast_sigmoid(float x) {
    return __fdividef(1.f, 1.f + __expf(-x));
}

// ---------------------------------------------------------------------------
__global__ void fold_kernel(const float* __restrict__ W_hh,
                            const float* __restrict__ W_sh)
{
    int idx = blockIdx.x * blockDim.x + threadIdx.x;
    if (idx >= PH * PVD) return;
    int j = idx >> 3, d = idx & 7;
    float s = 0.f;
    for (int k = 0; k < PH; k++)
        s = fmaf(W_hh[j * PH + k], W_sh[k * PVD + d], s);
    g_Wfold[idx] = s;
}

// ---------------------------------------------------------------------------
// GEMM (NT), f32x2 FMAs, double-buffered smem (unchanged from R9).
// ---------------------------------------------------------------------------
#define GEMM_HALF(curbuf, base)                                               \
    _Pragma("unroll")                                                         \
    for (int kk = (base); kk < (base) + 8; kk++) {                            \
        const float4* Arow = (const float4*)&As[curbuf][kk][0];               \
        float4 av0 = Arow[ty];                                                \
        float4 av1 = Arow[16 + ty];                                           \
        const ulonglong2* Brow = (const ulonglong2*)&Bs[curbuf][kk][0];       \
        ulonglong2 bp01 = Brow[tx];                                           \
        ulonglong2 bp23 = Brow[16 + tx];                                      \
        float a_[8] = {av0.x, av0.y, av0.z, av0.w, av1.x, av1.y, av1.z, av1.w};\
        _Pragma("unroll")                                                     \
        for (int i = 0; i < 8; i++) {                                         \
            unsigned long long ap;                                            \
            PACK2(ap, a_[i], a_[i]);                                          \
            FMA2(acc2[i][0], ap, bp01.x, acc2[i][0]);                         \
            FMA2(acc2[i][1], ap, bp01.y, acc2[i][1]);                         \
            FMA2(acc2[i][2], ap, bp23.x, acc2[i][2]);                         \
            FMA2(acc2[i][3], ap, bp23.y, acc2[i][3]);                         \
        }                                                                     \
    }

__global__ __launch_bounds__(256, 2) void gemm_nt(
    const float* __restrict__ A_in, const float* __restrict__ Bm,
    const float* __restrict__ bias1, const float* __restrict__ bias2,
    float* __restrict__ C_in, int M, int N, int K, int dstXp, int srcH)
{
    const float* A = srcH ? (const float*)g_H : A_in;
    float* C = dstXp ? (float*)g_Xp : C_in;

    __shared__ __align__(16) float As[2][16][132];
    __shared__ __align__(16) float Bs[2][16][132];

    const int tid = threadIdx.x;
    const int m0 = blockIdx.x * 128;
    const int n0 = blockIdx.y * 128;

    const int r = tid >> 2;
    const int c = (tid & 3) * 4;

    const float* Ap = A + (size_t)(m0 + r) * K + c;
    const float* Bp = Bm + (size_t)(n0 + r) * K + c;

    const int ty = tid >> 4;
    const int tx = tid & 15;

    unsigned long long acc2[8][4];
    #pragma unroll
    for (int i = 0; i < 8; i++)
        #pragma unroll
        for (int j = 0; j < 4; j++) acc2[i][j] = 0ull;

    {
        float4 a0 = *(const float4*)(Ap);
        float4 a1 = *(const float4*)(Ap + (size_t)64 * K);
        float4 b0 = *(const float4*)(Bp);
        float4 b1 = *(const float4*)(Bp + (size_t)64 * K);
        As[0][c+0][r] = a0.x; As[0][c+1][r] = a0.y; As[0][c+2][r] = a0.z; As[0][c+3][r] = a0.w;
        As[0][c+0][r+64] = a1.x; As[0][c+1][r+64] = a1.y; As[0][c+2][r+64] = a1.z; As[0][c+3][r+64] = a1.w;
        Bs[0][c+0][r] = b0.x; Bs[0][c+1][r] = b0.y; Bs[0][c+2][r] = b0.z; Bs[0][c+3][r] = b0.w;
        Bs[0][c+0][r+64] = b1.x; Bs[0][c+1][r+64] = b1.y; Bs[0][c+2][r+64] = b1.z; Bs[0][c+3][r+64] = b1.w;
    }
    __syncthreads();

    const int NT = K / 16;
    for (int it = 0; it < NT; it++) {
        const int cur = it & 1;
        const int nxt = cur ^ 1;
        const bool more = (it + 1 < NT);
        const int ko = (it + 1) * 16;

        float4 na0, nb0;
        if (more) {
            na0 = *(const float4*)(Ap + ko);
            nb0 = *(const float4*)(Bp + ko);
        }

        GEMM_HALF(cur, 0)

        float4 na1, nb1;
        if (more) {
            As[nxt][c+0][r] = na0.x; As[nxt][c+1][r] = na0.y;
            As[nxt][c+2][r] = na0.z; As[nxt][c+3][r] = na0.w;
            Bs[nxt][c+0][r] = nb0.x; Bs[nxt][c+1][r] = nb0.y;
            Bs[nxt][c+2][r] = nb0.z; Bs[nxt][c+3][r] = nb0.w;
            na1 = *(const float4*)(Ap + ko + (size_t)64 * K);
            nb1 = *(const float4*)(Bp + ko + (size_t)64 * K);
        }

        GEMM_HALF(cur, 8)

        if (more) {
            As[nxt][c+0][r+64] = na1.x; As[nxt][c+1][r+64] = na1.y;
            As[nxt][c+2][r+64] = na1.z; As[nxt][c+3][r+64] = na1.w;
            Bs[nxt][c+0][r+64] = nb1.x; Bs[nxt][c+1][r+64] = nb1.y;
            Bs[nxt][c+2][r+64] = nb1.z; Bs[nxt][c+3][r+64] = nb1.w;
        }
        __syncthreads();
    }

    const int nb0i = n0 + tx * 4;
    const int nb1i = n0 + 64 + tx * 4;
    float bs0[4], bs1[4];
    #pragma unroll
    for (int j = 0; j < 4; j++) {
        float b0v = 0.f, b1v = 0.f;
        if (bias1) { b0v += bias1[nb0i + j]; b1v += bias1[nb1i + j]; }
        if (bias2) { b0v += bias2[nb0i + j]; b1v += bias2[nb1i + j]; }
        bs0[j] = b0v; bs1[j] = b1v;
    }
    #pragma unroll
    for (int i = 0; i < 8; i++) {
        const int m = m0 + (i < 4 ? ty * 4 + i : 64 + ty * 4 + (i - 4));
        float v[8];
        #pragma unroll
        for (int j4 = 0; j4 < 4; j4++) UNPACK2(v[2*j4], v[2*j4+1], acc2[i][j4]);
        float4 o0 = make_float4(v[0]+bs0[0], v[1]+bs0[1], v[2]+bs0[2], v[3]+bs0[3]);
        float4 o1 = make_float4(v[4]+bs1[0], v[5]+bs1[1], v[6]+bs1[2], v[7]+bs1[3]);
        *(float4*)&C[(size_t)m * N + nb0i] = o0;
        *(float4*)&C[(size_t)m * N + nb1i] = o1;
    }
}

// ---------------------------------------------------------------------------
// Sequential scan — split-K pipelined (R9 skeleton), instruction-trimmed:
// float2 blend, f32x2 gate dots, q0/q1 parallel h stores, no-max softmax.
// ---------------------------------------------------------------------------
#define CH   36
#define HBUFN (8 * CH)
__device__ __forceinline__ int hidx(int k) { return (k >> 5) * CH + (k & 31); }

__global__ void __cluster_dims__(2, 1, 1) __launch_bounds__(512, 1)
scan_kernel(const float* __restrict__ stack0, const float* __restrict__ hidden0,
            const float* __restrict__ W_hh, const float* __restrict__ W_a,
            const float* __restrict__ W_n, float* __restrict__ out)
{
    __shared__ __align__(16) float sh_h[2][HBUFN];
    __shared__ __align__(8) float sh_stack[2][PD * PVD];
    __shared__ float sh_dots[11];
    __shared__ __align__(8) unsigned long long sh_bar;

    const int tid   = threadIdx.x;
    const int batch = blockIdx.x >> 1;
    const int half  = blockIdx.x & 1;
    const int jl    = tid >> 2;
    const int q     = tid & 3;
    const int jg    = half * 128 + jl;
    const int jgp   = hidx(jg);
    const int wid   = tid >> 5, lane = tid & 31;
    const int own_c0  = half * 4;
    const int peer_c0 = 4 - own_c0;

    unsigned long long wpo[16], wpp[16];
    {
        const float* wrow = W_hh + (size_t)jg * PH;
        const unsigned long long* wo = (const unsigned long long*)(wrow + half * 128 + 32 * q);
        const unsigned long long* wpr = (const unsigned long long*)(wrow + (1 - half) * 128 + 32 * q);
        #pragma unroll
        for (int i = 0; i < 16; i++) { wpo[i] = wo[i]; wpp[i] = wpr[i]; }
    }
    const float wf0 = g_Wfold[jg * PVD + 2 * q];
    const float wf1 = g_Wfold[jg * PVD + 2 * q + 1];

    // Packed gate weights: pair i covers chunks {2i, 2i+1};
    // lane L handles k = 64*i + 32*(L>>4) + 2*(L&15), two consecutive k.
    unsigned long long wan2[4];
    {
        const int row = (wid < 11) ? wid : 3;
        const float* wr = (row < 3) ? (W_a + row * PH) : (W_n + (row - 3) * PH);
        #pragma unroll
        for (int i = 0; i < 4; i++) {
            const int k = 64 * i + ((lane >> 4) << 5) + 2 * (lane & 15);
            PACK2(wan2[i], wr[k], wr[k + 1]);
        }
    }
    const int dotoff = ((lane >> 4) * CH) + 2 * (lane & 15);  // within chunk-pair

    if (tid < PH) sh_h[0][hidx(tid)] = hidden0[batch * PH + tid];
    for (int e = tid; e < PD * PVD; e += 512) sh_stack[0][e] = stack0[batch * PD * PVD + e];

    const uint32_t h_u32   = s2u(&sh_h[0][0]);
    const uint32_t bar_u32 = s2u(&sh_bar);
    uint32_t peer_h, peer_bar;
    const uint32_t prank = (uint32_t)(half ^ 1);
    asm("mapa.shared::cluster.u32 %0, %1, %2;" : "=r"(peer_h)   : "r"(h_u32),   "r"(prank));
    asm("mapa.shared::cluster.u32 %0, %1, %2;" : "=r"(peer_bar) : "r"(bar_u32), "r"(prank));

    if (tid == 0)
        asm volatile("mbarrier.init.shared.b64 [%0], 1;" :: "r"(bar_u32) : "memory");

    float xp_cur = 0.f;
    if (q < 2) xp_cur = g_Xp[((size_t)batch * PT) * PH + jg];

    __syncthreads();
    asm volatile("barrier.cluster.arrive.aligned;" ::: "memory");
    asm volatile("barrier.cluster.wait.aligned;"   ::: "memory");

    // Gates(h_{t-1}) carried for the deferred blend
    float ga0 = 0.f, ga1 = 0.f, ga2 = 1.f, gn0 = 0.f, gn1 = 0.f;

    for (int t = 0; t < PT; t++) {
        const int buf  = t & 1;
        const int nbuf = buf ^ 1;

        float xp_next = 0.f;
        if (q < 2 && t + 1 < PT)
            xp_next = g_Xp[((size_t)batch * PT + t + 1) * PH + jg];

        // ================= OWN PHASE =======================================
        unsigned long long a0 = 0ull, a1 = 0ull, a2 = 0ull, a3 = 0ull;
        {
            const ulonglong2* hv = (const ulonglong2*)&sh_h[buf][(own_c0 + q) * CH];
            #pragma unroll
            for (int i = 0; i < 8; i++) {
                ulonglong2 h = hv[i];
                FMA2(a0, wpo[2*i],   h.x, a0);
                FMA2(a1, wpo[2*i+1], h.y, a1);
            }
        }
        unsigned long long pd2 = 0ull;
        if (wid < 11) {
            #pragma unroll
            for (int i = 0; i < 2; i++) {
                unsigned long long hp = *(const unsigned long long*)
                    &sh_h[buf][(own_c0 + 2 * i) * CH + dotoff];
                FMA2(pd2, wan2[(own_c0 >> 1) + i], hp, pd2);
            }
        } else if ((wid == 12 || wid == 13) && t > 0) {
            const int i2 = (tid - 384) * 2;     // 0..126 even
            float2 v = make_float2(sh_h[buf][hidx(half * 128 + i2)],
                                   sh_h[buf][hidx(half * 128 + i2 + 1)]);
            *(float2*)&g_H[((size_t)batch * PT + t - 1) * PH + half * 128 + i2] = v;
        }
        // deferred float2 stack blend with gates(h_{t-1}): S[nbuf] -> S[buf]
        if (t > 0) {
            const int e0 = tid * 2;
            const int p  = e0 >> 3;
            float2 prev = *(const float2*)&sh_stack[nbuf][e0];
            float2 push = (p == 0) ? make_float2(gn0, gn1)
                                   : *(const float2*)&sh_stack[nbuf][e0 - 8];
            float2 pop  = (p == PD - 1) ? make_float2(0.f, 0.f)
                                        : *(const float2*)&sh_stack[nbuf][e0 + 8];
            float2 o;
            o.x = fmaf(ga0, push.x, fmaf(ga1, pop.x, ga2 * prev.x));
            o.y = fmaf(ga0, push.y, fmaf(ga1, pop.y, ga2 * prev.y));
            *(float2*)&sh_stack[buf][e0] = o;
        }

        // ================= WAIT for peer half of h_t =======================
        if (t > 0) {
            const uint32_t par = (uint32_t)((t - 1) & 1);
            uint32_t done;
            do {
                asm volatile("{\n\t.reg .pred P;\n\t"
                    "mbarrier.try_wait.parity.acquire.cluster.shared::cta.b64 P, [%1], %2, 0x989680;\n\t"
                    "selp.b32 %0, 1, 0, P;\n\t}"
                    : "=r"(done) : "r"(bar_u32), "r"(par) : "memory");
            } while (!done);
        }

        // ================= PEER PHASE ======================================
        {
            const ulonglong2* hv = (const ulonglong2*)&sh_h[buf][(peer_c0 + q) * CH];
            #pragma unroll
            for (int i = 0; i < 8; i++) {
                ulonglong2 h = hv[i];
                FMA2(a2, wpp[2*i],   h.x, a2);
                FMA2(a3, wpp[2*i+1], h.y, a3);
            }
        }
        if (wid < 11) {
            #pragma unroll
            for (int i = 0; i < 2; i++) {
                unsigned long long hp = *(const unsigned long long*)
                    &sh_h[buf][(peer_c0 + 2 * i) * CH + dotoff];
                FMA2(pd2, wan2[(peer_c0 >> 1) + i], hp, pd2);
            }
            float plo, phi; UNPACK2(plo, phi, pd2);
            float pdot = plo + phi;
            #pragma unroll
            for (int o = 16; o > 0; o >>= 1)
                pdot += __shfl_xor_sync(0xffffffffu, pdot, o);
            if (lane == 0) sh_dots[wid] = pdot;
        }
        __syncthreads();                       // sync1

        // ======= GATES: lane-split, no max-subtract ========================
        float A0, A1, A2, n0, n1;
        if (t == 0) {
            A0 = 0.f; A1 = 0.f; A2 = 1.f; n0 = 0.f; n1 = 0.f;
        } else {
            float arg;
            if (lane < 3)       arg = sh_dots[lane];
            else if (lane < 11) arg = -sh_dots[lane];
            else                arg = 0.f;
            const float e   = __expf(arg);
            const float sig = __fdividef(1.f, 1.f + e);   // lanes 3..10 valid
            const float e0 = __shfl_sync(0xffffffffu, e, 0);
            const float e1 = __shfl_sync(0xffffffffu, e, 1);
            const float e2 = __shfl_sync(0xffffffffu, e, 2);
            const float inv = __fdividef(1.f, e0 + e1 + e2);
            A0 = e0 * inv; A1 = e1 * inv; A2 = e2 * inv;
            n0 = __shfl_sync(0xffffffffu, sig, 3 + 2 * q);
            n1 = __shfl_sync(0xffffffffu, sig, 3 + 2 * q + 1);
        }
        ga0 = A0; ga1 = A1; ga2 = A2; gn0 = n0; gn1 = n1;

        ADD2(a0, a0, a1); ADD2(a2, a2, a3); ADD2(a0, a0, a2);
        float lo, hi; UNPACK2(lo, hi, a0);
        float acc = lo + hi;
        {
            const float s_t0 = sh_stack[buf][2 * q],     s_t1 = sh_stack[buf][2 * q + 1];
            const float s_b0 = sh_stack[buf][8 + 2 * q], s_b1 = sh_stack[buf][8 + 2 * q + 1];
            const float top0 = A0 * n0 + A1 * s_b0 + A2 * s_t0;
            const float top1 = A0 * n1 + A1 * s_b1 + A2 * s_t1;
            acc = fmaf(wf0, top0, acc);
            acc = fmaf(wf1, top1, acc);
        }
        acc += __shfl_xor_sync(0xffffffffu, acc, 1);
        acc += __shfl_xor_sync(0xffffffffu, acc, 2);
        if (q < 2) {
            const float hn = fast_tanh(acc + xp_cur);
            if (q == 0) {
                sh_h[nbuf][jgp] = hn;                    // local copy
            } else {
                asm volatile("st.shared::cluster.f32 [%0], %1;"   // peer copy
                             :: "r"(peer_h + (uint32_t)((nbuf * HBUFN + jgp) * 4)), "f"(hn)
                             : "memory");
            }
        }
        xp_cur = xp_next;
        __syncthreads();                       // sync2

        if (tid == 0)
            asm volatile("mbarrier.arrive.release.cluster.shared::cluster.b64 _, [%0];"
                         :: "r"(peer_bar) : "memory");
    }

    // ===================== EPILOGUE ========================================
    {
        const uint32_t par = (uint32_t)((PT - 1) & 1);
        uint32_t done;
        do {
            asm volatile("{\n\t.reg .pred P;\n\t"
                "mbarrier.try_wait.parity.acquire.cluster.shared::cta.b64 P, [%1], %2, 0x989680;\n\t"
                "selp.b32 %0, 1, 0, P;\n\t}"
                : "=r"(done) : "r"(bar_u32), "r"(par) : "memory");
        } while (!done);
    }
    // pending blend with gates(h_{PT-1}): S[1] -> S[0]  (= stack_{PT-1})
    {
        const int e0 = tid * 2;
        const int p  = e0 >> 3;
        float2 prev = *(const float2*)&sh_stack[1][e0];
        float2 push = (p == 0) ? make_float2(gn0, gn1)
                               : *(const float2*)&sh_stack[1][e0 - 8];
        float2 pop  = (p == PD - 1) ? make_float2(0.f, 0.f)
                                    : *(const float2*)&sh_stack[1][e0 + 8];
        float2 o;
        o.x = fmaf(ga0, push.x, fmaf(ga1, pop.x, ga2 * prev.x));
        o.y = fmaf(ga0, push.y, fmaf(ga1, pop.y, ga2 * prev.y));
        *(float2*)&sh_stack[0][e0] = o;
    }
    __syncthreads();
    // dots(h_PT) (h_PT full in sh_h[0] after the wait)
    if (wid < 11) {
        unsigned long long pd2 = 0ull;
        #pragma unroll
        for (int i = 0; i < 4; i++) {
            unsigned long long hp = *(const unsigned long long*)
                &sh_h[0][(2 * i) * CH + dotoff];
            FMA2(pd2, wan2[i], hp, pd2);
        }
        float plo, phi; UNPACK2(plo, phi, pd2);
        float p = plo + phi;
        #pragma unroll
        for (int o = 16; o > 0; o >>= 1)
            p += __shfl_xor_sync(0xffffffffu, p, o);
        if (lane == 0) sh_dots[wid] = p;
    } else if (wid == 12 || wid == 13) {
        const int i2 = (tid - 384) * 2;
        float2 v = make_float2(sh_h[0][hidx(half * 128 + i2)],
                               sh_h[0][hidx(half * 128 + i2 + 1)]);
        *(float2*)&g_H[((size_t)batch * PT + PT - 1) * PH + half * 128 + i2] = v;
    }
    __syncthreads();
    {   // final gates + blend: S[0] -> S[1] (= stack_PT)
        const float d0 = sh_dots[0], d1 = sh_dots[1], d2 = sh_dots[2];
        const float e0 = __expf(d0), e1 = __expf(d1), e2 = __expf(d2);
        const float inv = __fdividef(1.f, e0 + e1 + e2);
        const float A0 = e0 * inv, A1 = e1 * inv, A2 = e2 * inv;
        const float nb0 = fast_sigmoid(sh_dots[3 + 2 * (tid & 3)]);
        const float nb1 = fast_sigmoid(sh_dots[3 + 2 * (tid & 3) + 1]);
        __syncthreads();
        const int e0i = tid * 2;
        const int p   = e0i >> 3;
        float2 prev = *(const float2*)&sh_stack[0][e0i];
        float2 push = (p == 0) ? make_float2(nb0, nb1)
                               : *(const float2*)&sh_stack[0][e0i - 8];
        float2 pop  = (p == PD - 1) ? make_float2(0.f, 0.f)
                                    : *(const float2*)&sh_stack[0][e0i + 8];
        float2 o;
        o.x = fmaf(A0, push.x, fmaf(A1, pop.x, A2 * prev.x));
        o.y = fmaf(A0, push.y, fmaf(A1, pop.y, A2 * prev.y));
        *(float2*)&sh_stack[1][e0i] = o;
    }
    __syncthreads();

    const size_t OUT_Y = (size_t)PB * PT * PV;
    if (half == 0) {
        for (int e = tid; e < PD * PVD; e += 512)
            out[OUT_Y + (size_t)batch * PD * PVD + e] = sh_stack[1][e];
    }
    if (tid < 128) {
        const int row = half * 128 + tid;
        out[OUT_Y + (size_t)PB * PD * PVD + (size_t)batch * PH + row] =
            sh_h[0][hidx(row)];
    }

    asm volatile("barrier.cluster.arrive.aligned;" ::: "memory");
    asm volatile("barrier.cluster.wait.aligned;"   ::: "memory");
}

// ---------------------------------------------------------------------------
extern "C" void kernel_launch(void* const* d_in, const int* in_sizes, int n_in,
                              void* d_out, int out_size)
{
    const float* inputs  = (const float*)d_in[0];
    const float* stack0  = (const float*)d_in[1];
    const float* hidden0 = (const float*)d_in[2];
    const float* W_ih    = (const float*)d_in[3];
    const float* b_ih    = (const float*)d_in[4];
    const float* W_hh    = (const float*)d_in[5];
    const float* b_hh    = (const float*)d_in[6];
    const float* W_sh    = (const float*)d_in[7];
    const float* W_y     = (const float*)d_in[8];
    const float* W_a     = (const float*)d_in[9];
    const float* W_n     = (const float*)d_in[10];
    float* out = (float*)d_out;

    const int M = PB * PT;  // 131072

    fold_kernel<<<8, 256>>>(W_hh, W_sh);
    gemm_nt<<<dim3(M / 128, PH / 128), 256>>>(inputs, W_ih, b_ih, b_hh,
                                              nullptr, M, PH, PV, 1, 0);
    scan_kernel<<<2 * PB, 512>>>(stack0, hidden0, W_hh, W_a, W_n, out);
    gemm_nt<<<dim3(M / 128, PV / 128), 256>>>(nullptr, W_y, nullptr, nullptr,
                                              out, M, PV, PH, 0, 1);
}